// round 1
// baseline (speedup 1.0000x reference)
#include <cuda_runtime.h>
#include <math.h>

#define NNODES 100000
#define NEDGES 1000000
#define F0 256
#define F1 64
#define F2 40

// ---------------- scratch (static device globals; no allocation) ----------------
__device__ float d_deg[NNODES];
__device__ float d_g1[NNODES * F1];    // dinv[r] * (x @ W1)
__device__ float d_acc1[NNODES * F1];  // edge-scatter accumulator, layer 1
__device__ float d_h1[NNODES * F1];    // relu output of layer 1
__device__ float d_g2[NNODES * F2];    // dinv[r] * (h1 @ W2)
__device__ float d_acc2[NNODES * F2];  // edge-scatter accumulator, layer 2
__device__ float d_h2[NNODES * F2];    // pre-pairnorm layer-2 output
__device__ float d_colsum[64];
__device__ int   d_is64;

// ---------------- init: deg=1 (self loop), accumulators = 0 ----------------
__global__ void k_init() {
    int idx = blockIdx.x * blockDim.x + threadIdx.x;   // grid covers NNODES*F1
    if (idx < NNODES * F1) d_acc1[idx] = 0.f;
    if (idx < NNODES * F2) d_acc2[idx] = 0.f;
    if (idx < NNODES)      d_deg[idx]  = 1.0f;
    if (idx < 64)          d_colsum[idx] = 0.f;
}

// ---------------- detect int64 vs int32 edge indices ----------------
__global__ void k_detect(const long long* __restrict__ e) {
    __shared__ int bad;
    if (threadIdx.x == 0) bad = 0;
    __syncthreads();
    long long v = e[threadIdx.x];  // 256 entries; safe for both layouts
    if (v < 0 || v >= (long long)NNODES) atomicOr(&bad, 1);
    __syncthreads();
    if (threadIdx.x == 0) d_is64 = bad ? 0 : 1;
}

__device__ __forceinline__ int load_idx(const void* e, long long pos, int is64) {
    if (is64) return (int)((const long long*)e)[pos];
    return ((const int*)e)[pos];
}

// ---------------- degree: atomic count of incoming edges ----------------
__global__ void k_deg(const void* __restrict__ eidx) {
    int e = blockIdx.x * blockDim.x + threadIdx.x;
    if (e >= NEDGES) return;
    int is64 = d_is64;
    int dst = load_idx(eidx, (long long)NEDGES + e, is64);
    atomicAdd(&d_deg[dst], 1.0f);
}

// ---------------- tiled SGEMM with row-scale epilogue: C = rsqrt(deg[r]) * (A@B) ----------------
// BM=64, BN=64, BK=16, TM=TN=4, 256 threads. N <= 64, K multiple of 16.
__global__ void k_gemm_rowscale(const float* __restrict__ A, const float* __restrict__ B,
                                float* __restrict__ C, int M, int N, int K) {
    const int BM = 64, BN = 64, BK = 16, TM = 4, TN = 4;
    __shared__ float As[BK][BM];
    __shared__ float Bs[BK][BN];
    int tid = threadIdx.x;
    int rowBase = blockIdx.x * BM;
    int tr = tid / (BN / TN);        // 0..15
    int tc = tid % (BN / TN);        // 0..15
    float acc[TM][TN];
#pragma unroll
    for (int i = 0; i < TM; i++)
#pragma unroll
        for (int j = 0; j < TN; j++) acc[i][j] = 0.f;

    int aRow = tid / (BK / 4);       // 0..63
    int aCol = (tid % (BK / 4)) * 4; // 0,4,8,12

    for (int k0 = 0; k0 < K; k0 += BK) {
        // A tile (float4, row-guarded)
        float4 av = make_float4(0.f, 0.f, 0.f, 0.f);
        int gr = rowBase + aRow;
        if (gr < M) av = *(const float4*)(A + (size_t)gr * K + k0 + aCol);
        As[aCol + 0][aRow] = av.x;
        As[aCol + 1][aRow] = av.y;
        As[aCol + 2][aRow] = av.z;
        As[aCol + 3][aRow] = av.w;
        // B tile (scalar, col-guarded for N<64)
#pragma unroll
        for (int i = 0; i < (BK * BN) / 256; i++) {
            int li = tid + i * 256;
            int br = li / BN, bc = li % BN;
            Bs[br][bc] = (bc < N) ? B[(size_t)(k0 + br) * N + bc] : 0.f;
        }
        __syncthreads();
#pragma unroll
        for (int k = 0; k < BK; k++) {
            float rm[TM], rn[TN];
#pragma unroll
            for (int i = 0; i < TM; i++) rm[i] = As[k][tr * TM + i];
#pragma unroll
            for (int j = 0; j < TN; j++) rn[j] = Bs[k][tc * TN + j];
#pragma unroll
            for (int i = 0; i < TM; i++)
#pragma unroll
                for (int j = 0; j < TN; j++) acc[i][j] += rm[i] * rn[j];
        }
        __syncthreads();
    }
#pragma unroll
    for (int i = 0; i < TM; i++) {
        int r = rowBase + tr * TM + i;
        if (r >= M) continue;
        float s = rsqrtf(d_deg[r]);
#pragma unroll
        for (int j = 0; j < TN; j++) {
            int c = tc * TN + j;
            if (c < N) C[(size_t)r * N + c] = acc[i][j] * s;
        }
    }
}

// ---------------- edge scatter: acc[dst] += g[src], vectorized float4 RED ----------------
template <int F>
__global__ void k_scatter(const float* __restrict__ g, float* __restrict__ acc,
                          const void* __restrict__ eidx) {
    const int CH = F / 4;
    long long idx = (long long)blockIdx.x * blockDim.x + threadIdx.x;
    if (idx >= (long long)NEDGES * CH) return;
    int e = (int)(idx / CH);
    int c = (int)(idx % CH);
    int is64 = d_is64;
    int src = load_idx(eidx, e, is64);
    int dst = load_idx(eidx, (long long)NEDGES + e, is64);
    float4 v = *(const float4*)(g + (size_t)src * F + c * 4);
    float* p = acc + (size_t)dst * F + c * 4;
    asm volatile("red.global.add.v4.f32 [%0], {%1,%2,%3,%4};"
                 :: "l"(p), "f"(v.x), "f"(v.y), "f"(v.z), "f"(v.w) : "memory");
}

// ---------------- layer-1 epilogue: h1 = relu(dinv*(acc+g) + b1) ----------------
__global__ void k_post1(const float* __restrict__ b1) {
    int idx = blockIdx.x * blockDim.x + threadIdx.x;
    if (idx >= NNODES * F1) return;
    int r = idx >> 6;          // /64
    int c = idx & 63;
    float v = rsqrtf(d_deg[r]) * (d_acc1[idx] + d_g1[idx]) + b1[c];
    d_h1[idx] = fmaxf(v, 0.f);
}

// ---------------- layer-2 epilogue: h2 = dinv*(acc+g) + b2, plus column sums ----------------
__global__ void k_post2(const float* __restrict__ b2) {
    __shared__ float scol[F2];
    int t = threadIdx.x;
    if (t < F2) scol[t] = 0.f;
    __syncthreads();
    int idx = blockIdx.x * blockDim.x + t;
    if (idx < NNODES * F2) {
        int r = idx / F2;
        int c = idx % F2;
        float v = rsqrtf(d_deg[r]) * (d_acc2[idx] + d_g2[idx]) + b2[c];
        d_h2[idx] = v;
        atomicAdd(&scol[c], v);
    }
    __syncthreads();
    if (t < F2) atomicAdd(&d_colsum[t], scol[t]);
}

// ---------------- PairNorm-SI + log_softmax, one warp per row ----------------
__global__ void k_final(float* __restrict__ out) {
    int gt = blockIdx.x * blockDim.x + threadIdx.x;
    int row = gt >> 5;
    int lane = gt & 31;
    if (row >= NNODES) return;
    const float invN = 1.0f / (float)NNODES;
    bool has2 = lane < (F2 - 32);  // lanes 0..7 hold cols 32..39
    float y0 = d_h2[(size_t)row * F2 + lane] - d_colsum[lane] * invN;
    float y1 = 0.f;
    if (has2) y1 = d_h2[(size_t)row * F2 + 32 + lane] - d_colsum[32 + lane] * invN;
    float ss = y0 * y0 + y1 * y1;
#pragma unroll
    for (int o = 16; o; o >>= 1) ss += __shfl_xor_sync(0xffffffffu, ss, o);
    float inv = rsqrtf(1e-6f + ss);
    float z0 = y0 * inv;
    float z1 = has2 ? y1 * inv : -1e30f;
    float mx = fmaxf(z0, z1);
#pragma unroll
    for (int o = 16; o; o >>= 1) mx = fmaxf(mx, __shfl_xor_sync(0xffffffffu, mx, o));
    float se = expf(z0 - mx) + (has2 ? expf(z1 - mx) : 0.f);
#pragma unroll
    for (int o = 16; o; o >>= 1) se += __shfl_xor_sync(0xffffffffu, se, o);
    float lse = logf(se);
    out[(size_t)row * F2 + lane] = z0 - mx - lse;
    if (has2) out[(size_t)row * F2 + 32 + lane] = z1 - mx - lse;
}

// ---------------- launch ----------------
extern "C" void kernel_launch(void* const* d_in, const int* in_sizes, int n_in,
                              void* d_out, int out_size) {
    const float* x   = (const float*)d_in[0];
    const void*  eix = d_in[1];
    const float* W1  = (const float*)d_in[2];
    const float* b1  = (const float*)d_in[3];
    const float* W2  = (const float*)d_in[4];
    const float* b2  = (const float*)d_in[5];
    float* out = (float*)d_out;

    float *g1, *a1, *h1, *g2, *a2;
    cudaGetSymbolAddress((void**)&g1, d_g1);
    cudaGetSymbolAddress((void**)&a1, d_acc1);
    cudaGetSymbolAddress((void**)&h1, d_h1);
    cudaGetSymbolAddress((void**)&g2, d_g2);
    cudaGetSymbolAddress((void**)&a2, d_acc2);

    const int T = 256;
    k_init<<<(NNODES * F1 + T - 1) / T, T>>>();
    k_detect<<<1, 256>>>((const long long*)eix);
    k_deg<<<(NEDGES + T - 1) / T, T>>>(eix);

    // Layer 1
    k_gemm_rowscale<<<(NNODES + 63) / 64, 256>>>(x, W1, g1, NNODES, F1, F0);
    {
        long long n = (long long)NEDGES * (F1 / 4);
        k_scatter<F1><<<(unsigned)((n + T - 1) / T), T>>>(g1, a1, eix);
    }
    k_post1<<<(NNODES * F1 + T - 1) / T, T>>>(b1);

    // Layer 2
    k_gemm_rowscale<<<(NNODES + 63) / 64, 256>>>(h1, W2, g2, NNODES, F2, F1);
    {
        long long n = (long long)NEDGES * (F2 / 4);
        k_scatter<F2><<<(unsigned)((n + T - 1) / T), T>>>(g2, a2, eix);
    }
    k_post2<<<(NNODES * F2 + T - 1) / T, T>>>(b2);

    // PairNorm + log_softmax
    k_final<<<((long long)NNODES * 32 + T - 1) / T, T>>>(out);
}

// round 2
// speedup vs baseline: 1.2443x; 1.2443x over previous
#include <cuda_runtime.h>
#include <math.h>

#define NNODES 100000
#define NEDGES 1000000
#define F0 256
#define F1 64
#define F2 40

// ---------------- scratch (static device globals; no allocation) ----------------
__device__ float d_deg[NNODES];
__device__ float d_g1[NNODES * F1];    // dinv[r] * (x @ W1)  (gather source)
__device__ float d_acc1[NNODES * F1];  // scatter accumulator, init = g1 (self loop)
__device__ float d_h1[NNODES * F1];    // relu output of layer 1
__device__ float d_g2[NNODES * F2];
__device__ float d_acc2[NNODES * F2];
__device__ float d_h2[NNODES * F2];
__device__ float d_colsum[64];
__device__ int   d_is64;
__device__ int   d_e32[2 * NEDGES];    // converted int32 indices: [src | dst]

// ---------------- tiny init: deg=1 (self loop), colsum=0 ----------------
__global__ void k_init() {
    int idx = blockIdx.x * blockDim.x + threadIdx.x;
    if (idx < NNODES) d_deg[idx] = 1.0f;
    if (idx < 64)     d_colsum[idx] = 0.f;
}

// ---------------- detect int64 vs int32 edge indices ----------------
__global__ void k_detect(const long long* __restrict__ e) {
    __shared__ int bad;
    if (threadIdx.x == 0) bad = 0;
    __syncthreads();
    long long v = e[threadIdx.x];  // 256 entries; in-bounds for both layouts
    if (v < 0 || v >= (long long)NNODES) atomicOr(&bad, 1);
    __syncthreads();
    if (threadIdx.x == 0) d_is64 = bad ? 0 : 1;
}

// ---------------- convert indices to int32 once ----------------
__global__ void k_cvt(const void* __restrict__ e) {
    int idx = blockIdx.x * blockDim.x + threadIdx.x;
    if (idx >= 2 * NEDGES) return;
    int v = d_is64 ? (int)((const long long*)e)[idx] : ((const int*)e)[idx];
    d_e32[idx] = v;
}

// ---------------- degree: atomic count of incoming edges ----------------
__global__ void k_deg() {
    int e = blockIdx.x * blockDim.x + threadIdx.x;
    if (e >= NEDGES) return;
    atomicAdd(&d_deg[d_e32[NEDGES + e]], 1.0f);
}

// ---------------- SGEMM, BM=128 BN=64 BK=16, TM=8 TN=4, 256 thr ----------------
// C = Cacc = rsqrt(deg[r]) * (A@B).  All smem compute traffic is LDS.128.
__global__ __launch_bounds__(256) void k_gemm_rowscale(
    const float* __restrict__ A, const float* __restrict__ B,
    float* __restrict__ C, float* __restrict__ Cacc, int M, int N, int K) {
    const int BM = 128, BK = 16, BN = 64;
    __shared__ float As[BK][BM + 4];   // +4 pad: 16B-aligned rows, low store conflicts
    __shared__ float Bs[BK][BN];
    int tid = threadIdx.x;
    int rowBase = blockIdx.x * BM;
    int tr = tid >> 4;                 // 0..15 -> rows tr*8..+7
    int tc = tid & 15;                 // 0..15 -> cols tc*4..+3

    float acc[8][4];
#pragma unroll
    for (int i = 0; i < 8; i++)
#pragma unroll
        for (int j = 0; j < 4; j++) acc[i][j] = 0.f;

    for (int k0 = 0; k0 < K; k0 += BK) {
        // A tile: 128x16 = 512 float4s, 2 per thread, stored transposed
#pragma unroll
        for (int v = 0; v < 2; v++) {
            int vec = tid + v * 256;
            int row = vec >> 2;
            int col = (vec & 3) * 4;
            float4 av = make_float4(0.f, 0.f, 0.f, 0.f);
            int gr = rowBase + row;
            if (gr < M) av = *(const float4*)(A + (size_t)gr * K + k0 + col);
            As[col + 0][row] = av.x;
            As[col + 1][row] = av.y;
            As[col + 2][row] = av.z;
            As[col + 3][row] = av.w;
        }
        // B tile: 16x64 = 256 float4s, 1 per thread
        {
            int br = tid >> 4;
            int bc = (tid & 15) * 4;
            float4 bv = make_float4(0.f, 0.f, 0.f, 0.f);
            if (bc < N) bv = *(const float4*)(B + (size_t)(k0 + br) * N + bc);
            *(float4*)&Bs[br][bc] = bv;
        }
        __syncthreads();
#pragma unroll
        for (int k = 0; k < BK; k++) {
            float4 a0 = *(const float4*)&As[k][tr * 8];
            float4 a1 = *(const float4*)&As[k][tr * 8 + 4];
            float4 bv = *(const float4*)&Bs[k][tc * 4];
            float am[8] = {a0.x, a0.y, a0.z, a0.w, a1.x, a1.y, a1.z, a1.w};
            float bn[4] = {bv.x, bv.y, bv.z, bv.w};
#pragma unroll
            for (int i = 0; i < 8; i++)
#pragma unroll
                for (int j = 0; j < 4; j++) acc[i][j] += am[i] * bn[j];
        }
        __syncthreads();
    }
    int cc = tc * 4;
    if (cc < N) {
#pragma unroll
        for (int i = 0; i < 8; i++) {
            int r = rowBase + tr * 8 + i;
            if (r >= M) break;
            float s = rsqrtf(d_deg[r]);
            float4 o = make_float4(acc[i][0] * s, acc[i][1] * s, acc[i][2] * s, acc[i][3] * s);
            *(float4*)(C    + (size_t)r * N + cc) = o;
            *(float4*)(Cacc + (size_t)r * N + cc) = o;
        }
    }
}

// ---------------- edge scatter: acc[dst] += g[src], float4 RED ----------------
template <int F>
__global__ void k_scatter(const float* __restrict__ g, float* __restrict__ acc) {
    const int CH = F / 4;
    long long idx = (long long)blockIdx.x * blockDim.x + threadIdx.x;
    if (idx >= (long long)NEDGES * CH) return;
    int e = (int)(idx / CH);
    int c = (int)(idx % CH);
    int src = d_e32[e];
    int dst = d_e32[NEDGES + e];
    float4 v = *(const float4*)(g + (size_t)src * F + c * 4);
    float* p = acc + (size_t)dst * F + c * 4;
    asm volatile("red.global.add.v4.f32 [%0], {%1,%2,%3,%4};"
                 :: "l"(p), "f"(v.x), "f"(v.y), "f"(v.z), "f"(v.w) : "memory");
}

// ---------------- layer-1 epilogue: h1 = relu(dinv*acc + b1), float4 ----------------
__global__ void k_post1(const float* __restrict__ b1) {
    int idx = blockIdx.x * blockDim.x + threadIdx.x;   // over NNODES*16
    if (idx >= NNODES * (F1 / 4)) return;
    int r = idx >> 4;
    int c = (idx & 15) * 4;
    float s = rsqrtf(d_deg[r]);
    float4 a = *(const float4*)&d_acc1[(size_t)idx * 4];
    float4 o;
    o.x = fmaxf(s * a.x + __ldg(b1 + c + 0), 0.f);
    o.y = fmaxf(s * a.y + __ldg(b1 + c + 1), 0.f);
    o.z = fmaxf(s * a.z + __ldg(b1 + c + 2), 0.f);
    o.w = fmaxf(s * a.w + __ldg(b1 + c + 3), 0.f);
    *(float4*)&d_h1[(size_t)idx * 4] = o;
}

// ---------------- layer-2 epilogue: h2 = dinv*acc + b2, plus column sums ----------------
__global__ void k_post2(const float* __restrict__ b2) {
    __shared__ float scol[F2];
    int t = threadIdx.x;
    if (t < F2) scol[t] = 0.f;
    __syncthreads();
    int idx = blockIdx.x * blockDim.x + t;             // over NNODES*10
    if (idx < NNODES * (F2 / 4)) {
        int r = idx / 10;
        int c = (idx % 10) * 4;
        float s = rsqrtf(d_deg[r]);
        float4 a = *(const float4*)&d_acc2[(size_t)idx * 4];
        float4 o;
        o.x = s * a.x + __ldg(b2 + c + 0);
        o.y = s * a.y + __ldg(b2 + c + 1);
        o.z = s * a.z + __ldg(b2 + c + 2);
        o.w = s * a.w + __ldg(b2 + c + 3);
        *(float4*)&d_h2[(size_t)idx * 4] = o;
        atomicAdd(&scol[c + 0], o.x);
        atomicAdd(&scol[c + 1], o.y);
        atomicAdd(&scol[c + 2], o.z);
        atomicAdd(&scol[c + 3], o.w);
    }
    __syncthreads();
    if (t < F2) atomicAdd(&d_colsum[t], scol[t]);
}

// ---------------- PairNorm-SI + log_softmax, one warp per row ----------------
__global__ void k_final(float* __restrict__ out) {
    int gt = blockIdx.x * blockDim.x + threadIdx.x;
    int row = gt >> 5;
    int lane = gt & 31;
    if (row >= NNODES) return;
    const float invN = 1.0f / (float)NNODES;
    bool has2 = lane < (F2 - 32);
    float y0 = d_h2[(size_t)row * F2 + lane] - d_colsum[lane] * invN;
    float y1 = 0.f;
    if (has2) y1 = d_h2[(size_t)row * F2 + 32 + lane] - d_colsum[32 + lane] * invN;
    float ss = y0 * y0 + y1 * y1;
#pragma unroll
    for (int o = 16; o; o >>= 1) ss += __shfl_xor_sync(0xffffffffu, ss, o);
    float inv = rsqrtf(1e-6f + ss);
    float z0 = y0 * inv;
    float z1 = has2 ? y1 * inv : -1e30f;
    float mx = fmaxf(z0, z1);
#pragma unroll
    for (int o = 16; o; o >>= 1) mx = fmaxf(mx, __shfl_xor_sync(0xffffffffu, mx, o));
    float se = expf(z0 - mx) + (has2 ? expf(z1 - mx) : 0.f);
#pragma unroll
    for (int o = 16; o; o >>= 1) se += __shfl_xor_sync(0xffffffffu, se, o);
    float lse = logf(se);
    out[(size_t)row * F2 + lane] = z0 - mx - lse;
    if (has2) out[(size_t)row * F2 + 32 + lane] = z1 - mx - lse;
}

// ---------------- launch ----------------
extern "C" void kernel_launch(void* const* d_in, const int* in_sizes, int n_in,
                              void* d_out, int out_size) {
    const float* x   = (const float*)d_in[0];
    const void*  eix = d_in[1];
    const float* W1  = (const float*)d_in[2];
    const float* b1  = (const float*)d_in[3];
    const float* W2  = (const float*)d_in[4];
    const float* b2  = (const float*)d_in[5];
    float* out = (float*)d_out;

    float *g1, *a1, *h1, *g2, *a2;
    cudaGetSymbolAddress((void**)&g1, d_g1);
    cudaGetSymbolAddress((void**)&a1, d_acc1);
    cudaGetSymbolAddress((void**)&h1, d_h1);
    cudaGetSymbolAddress((void**)&g2, d_g2);
    cudaGetSymbolAddress((void**)&a2, d_acc2);

    const int T = 256;
    k_init<<<(NNODES + T - 1) / T, T>>>();
    k_detect<<<1, 256>>>((const long long*)eix);
    k_cvt<<<(2 * NEDGES + T - 1) / T, T>>>(eix);
    k_deg<<<(NEDGES + T - 1) / T, T>>>();

    // Layer 1
    k_gemm_rowscale<<<(NNODES + 127) / 128, 256>>>(x, W1, g1, a1, NNODES, F1, F0);
    {
        long long n = (long long)NEDGES * (F1 / 4);
        k_scatter<F1><<<(unsigned)((n + T - 1) / T), T>>>(g1, a1);
    }
    k_post1<<<(NNODES * (F1 / 4) + T - 1) / T, T>>>(b1);

    // Layer 2
    k_gemm_rowscale<<<(NNODES + 127) / 128, 256>>>(h1, W2, g2, a2, NNODES, F2, F1);
    {
        long long n = (long long)NEDGES * (F2 / 4);
        k_scatter<F2><<<(unsigned)((n + T - 1) / T), T>>>(g2, a2);
    }
    k_post2<<<(NNODES * (F2 / 4) + T - 1) / T, T>>>(b2);

    // PairNorm + log_softmax
    k_final<<<((long long)NNODES * 32 + T - 1) / T, T>>>(out);
}

// round 5
// speedup vs baseline: 1.6212x; 1.3029x over previous
#include <cuda_runtime.h>
#include <math.h>

#define NNODES 100000
#define NEDGES 1000000
#define F0 256
#define F1 64
#define F2 40
#define SCAN_B 512
#define NB ((NNODES + SCAN_B - 1) / SCAN_B)   // 196

// ---------------- scratch (static device globals; no allocation) ----------------
__device__ float d_g1[NNODES * F1];    // dinv[r] * (x @ W1)
__device__ float d_h1[NNODES * F1];    // relu layer-1 output
__device__ float d_g2[NNODES * F2];
__device__ float d_h2[NNODES * F2];
__device__ float d_colsum[64];
__device__ float d_dinv[NNODES];
__device__ int   d_is64;
__device__ int   d_src32[NEDGES];
__device__ int   d_dst32[NEDGES];
__device__ int   d_csrc[NEDGES];       // CSR-by-dst: src ids
__device__ int   d_cnt[NNODES];
__device__ int   d_rowptr[NNODES + 1];
__device__ int   d_cursor[NNODES];
__device__ int   d_blocksum[NB];

// ---------------- init ----------------
__global__ void k_init() {
    int i = blockIdx.x * blockDim.x + threadIdx.x;
    if (i < NNODES) d_cnt[i] = 0;
    if (i < 64)     d_colsum[i] = 0.f;
}

// ---------------- detect int64 vs int32 edge indices ----------------
__global__ void k_detect(const long long* __restrict__ e) {
    __shared__ int bad;
    if (threadIdx.x == 0) bad = 0;
    __syncthreads();
    long long v = e[threadIdx.x];
    if (v < 0 || v >= (long long)NNODES) atomicOr(&bad, 1);
    __syncthreads();
    if (threadIdx.x == 0) d_is64 = bad ? 0 : 1;
}

// ---------------- convert + per-dst histogram ----------------
__global__ void k_cvt_count(const void* __restrict__ e) {
    int idx = blockIdx.x * blockDim.x + threadIdx.x;
    if (idx >= NEDGES) return;
    int is64 = d_is64;
    int s, d;
    if (is64) {
        s = (int)((const long long*)e)[idx];
        d = (int)((const long long*)e)[NEDGES + idx];
    } else {
        s = ((const int*)e)[idx];
        d = ((const int*)e)[NEDGES + idx];
    }
    d_src32[idx] = s;
    d_dst32[idx] = d;
    atomicAdd(&d_cnt[d], 1);
}

// ---------------- 3-kernel exclusive scan of d_cnt -> d_rowptr ----------------
__global__ void k_scan1() {
    __shared__ int sm[SCAN_B];
    int base = blockIdx.x * SCAN_B;
    int t = threadIdx.x;
    int v = (base + t < NNODES) ? d_cnt[base + t] : 0;
    sm[t] = v;
    __syncthreads();
    for (int o = 1; o < SCAN_B; o <<= 1) {
        int a = (t >= o) ? sm[t - o] : 0;
        __syncthreads();
        sm[t] += a;
        __syncthreads();
    }
    if (base + t < NNODES) d_rowptr[base + t] = sm[t] - v;  // partial exclusive
    if (t == SCAN_B - 1) d_blocksum[blockIdx.x] = sm[t];
}

__global__ void k_scan2() {
    __shared__ int sm[256];
    int t = threadIdx.x;
    int v = (t < NB) ? d_blocksum[t] : 0;
    sm[t] = v;
    __syncthreads();
    for (int o = 1; o < 256; o <<= 1) {
        int a = (t >= o) ? sm[t - o] : 0;
        __syncthreads();
        sm[t] += a;
        __syncthreads();
    }
    if (t < NB) d_blocksum[t] = sm[t] - v;  // exclusive block offsets
}

__global__ void k_scan3() {
    int i = blockIdx.x * blockDim.x + threadIdx.x;
    if (i >= NNODES) return;
    int rp = d_rowptr[i] + d_blocksum[i / SCAN_B];
    d_rowptr[i] = rp;
    d_cursor[i] = rp;
    d_dinv[i] = rsqrtf(1.0f + (float)d_cnt[i]);   // deg includes self loop
    if (i == 0) d_rowptr[NNODES] = NEDGES;
}

// ---------------- fill CSR ----------------
__global__ void k_fill() {
    int idx = blockIdx.x * blockDim.x + threadIdx.x;
    if (idx >= NEDGES) return;
    int dst = d_dst32[idx];
    int pos = atomicAdd(&d_cursor[dst], 1);
    d_csrc[pos] = d_src32[idx];
}

// ---------------- SGEMM, BM=128 BN=64 BK=16, TM=8 TN=4, 256 thr ----------------
// C = dinv[r] * (A@B).  All smem compute traffic is LDS.128.
__global__ __launch_bounds__(256) void k_gemm_rowscale(
    const float* __restrict__ A, const float* __restrict__ B,
    float* __restrict__ C, int M, int N, int K) {
    const int BM = 128, BK = 16, BN = 64;
    __shared__ float As[BK][BM + 4];
    __shared__ float Bs[BK][BN];
    int tid = threadIdx.x;
    int rowBase = blockIdx.x * BM;
    int tr = tid >> 4;
    int tc = tid & 15;

    float acc[8][4];
#pragma unroll
    for (int i = 0; i < 8; i++)
#pragma unroll
        for (int j = 0; j < 4; j++) acc[i][j] = 0.f;

    for (int k0 = 0; k0 < K; k0 += BK) {
#pragma unroll
        for (int v = 0; v < 2; v++) {
            int vec = tid + v * 256;
            int row = vec >> 2;
            int col = (vec & 3) * 4;
            float4 av = make_float4(0.f, 0.f, 0.f, 0.f);
            int gr = rowBase + row;
            if (gr < M) av = *(const float4*)(A + (size_t)gr * K + k0 + col);
            As[col + 0][row] = av.x;
            As[col + 1][row] = av.y;
            As[col + 2][row] = av.z;
            As[col + 3][row] = av.w;
        }
        {
            int br = tid >> 4;
            int bc = (tid & 15) * 4;
            float4 bv = make_float4(0.f, 0.f, 0.f, 0.f);
            if (bc < N) bv = *(const float4*)(B + (size_t)(k0 + br) * N + bc);
            *(float4*)&Bs[br][bc] = bv;
        }
        __syncthreads();
#pragma unroll
        for (int k = 0; k < BK; k++) {
            float4 a0 = *(const float4*)&As[k][tr * 8];
            float4 a1 = *(const float4*)&As[k][tr * 8 + 4];
            float4 bv = *(const float4*)&Bs[k][tc * 4];
            float am[8] = {a0.x, a0.y, a0.z, a0.w, a1.x, a1.y, a1.z, a1.w};
            float bn[4] = {bv.x, bv.y, bv.z, bv.w};
#pragma unroll
            for (int i = 0; i < 8; i++)
#pragma unroll
                for (int j = 0; j < 4; j++) acc[i][j] += am[i] * bn[j];
        }
        __syncthreads();
    }
    int cc = tc * 4;
    if (cc < N) {
#pragma unroll
        for (int i = 0; i < 8; i++) {
            int r = rowBase + tr * 8 + i;
            if (r >= M) break;
            float s = d_dinv[r];
            float4 o = make_float4(acc[i][0] * s, acc[i][1] * s, acc[i][2] * s, acc[i][3] * s);
            *(float4*)(C + (size_t)r * N + cc) = o;
        }
    }
}

// ---------------- layer-1 aggregation: gather + self loop + bias + relu ----------------
// 16 lanes per node, each lane one float4 chunk of the 64-float row.
__global__ __launch_bounds__(256) void k_agg1(const float* __restrict__ b1) {
    int g = (blockIdx.x * blockDim.x + threadIdx.x) >> 4;
    int lane = threadIdx.x & 15;
    if (g >= NNODES) return;
    int start = d_rowptr[g];
    int end = d_rowptr[g + 1];
    const float4* G = (const float4*)d_g1;
    float4 acc = __ldg(&G[(size_t)g * 16 + lane]);   // self loop
    int e = start;
    for (; e + 1 < end; e += 2) {
        int s0 = __ldg(&d_csrc[e]);
        int s1 = __ldg(&d_csrc[e + 1]);
        float4 v0 = __ldg(&G[(size_t)s0 * 16 + lane]);
        float4 v1 = __ldg(&G[(size_t)s1 * 16 + lane]);
        acc.x += v0.x + v1.x;
        acc.y += v0.y + v1.y;
        acc.z += v0.z + v1.z;
        acc.w += v0.w + v1.w;
    }
    if (e < end) {
        int s0 = __ldg(&d_csrc[e]);
        float4 v = __ldg(&G[(size_t)s0 * 16 + lane]);
        acc.x += v.x; acc.y += v.y; acc.z += v.z; acc.w += v.w;
    }
    float s = d_dinv[g];
    int c = lane * 4;
    float4 o;
    o.x = fmaxf(s * acc.x + __ldg(b1 + c + 0), 0.f);
    o.y = fmaxf(s * acc.y + __ldg(b1 + c + 1), 0.f);
    o.z = fmaxf(s * acc.z + __ldg(b1 + c + 2), 0.f);
    o.w = fmaxf(s * acc.w + __ldg(b1 + c + 3), 0.f);
    ((float4*)d_h1)[(size_t)g * 16 + lane] = o;
}

// ---------------- layer-2 aggregation: gather + self loop + bias + column sums ----------------
// 16 lanes per node, lanes 0-9 active (10 float4 chunks of the 40-float row).
__global__ __launch_bounds__(256) void k_agg2(const float* __restrict__ b2) {
    __shared__ float scol[F2];
    int t = threadIdx.x;
    if (t < F2) scol[t] = 0.f;
    __syncthreads();
    int g = (blockIdx.x * blockDim.x + t) >> 4;
    int lane = t & 15;
    bool active = (g < NNODES) && (lane < 10);
    if (active) {
        int start = d_rowptr[g];
        int end = d_rowptr[g + 1];
        const float4* G = (const float4*)d_g2;
        float4 acc = __ldg(&G[(size_t)g * 10 + lane]);   // self loop
        int e = start;
        for (; e + 1 < end; e += 2) {
            int s0 = __ldg(&d_csrc[e]);
            int s1 = __ldg(&d_csrc[e + 1]);
            float4 v0 = __ldg(&G[(size_t)s0 * 10 + lane]);
            float4 v1 = __ldg(&G[(size_t)s1 * 10 + lane]);
            acc.x += v0.x + v1.x;
            acc.y += v0.y + v1.y;
            acc.z += v0.z + v1.z;
            acc.w += v0.w + v1.w;
        }
        if (e < end) {
            int s0 = __ldg(&d_csrc[e]);
            float4 v = __ldg(&G[(size_t)s0 * 10 + lane]);
            acc.x += v.x; acc.y += v.y; acc.z += v.z; acc.w += v.w;
        }
        float s = d_dinv[g];
        int c = lane * 4;
        float4 o;
        o.x = s * acc.x + __ldg(b2 + c + 0);
        o.y = s * acc.y + __ldg(b2 + c + 1);
        o.z = s * acc.z + __ldg(b2 + c + 2);
        o.w = s * acc.w + __ldg(b2 + c + 3);
        ((float4*)d_h2)[(size_t)g * 10 + lane] = o;
        atomicAdd(&scol[c + 0], o.x);
        atomicAdd(&scol[c + 1], o.y);
        atomicAdd(&scol[c + 2], o.z);
        atomicAdd(&scol[c + 3], o.w);
    }
    __syncthreads();
    if (t < F2) atomicAdd(&d_colsum[t], scol[t]);
}

// ---------------- PairNorm-SI + log_softmax, one warp per row ----------------
__global__ void k_final(float* __restrict__ out) {
    int gt = blockIdx.x * blockDim.x + threadIdx.x;
    int row = gt >> 5;
    int lane = gt & 31;
    if (row >= NNODES) return;
    const float invN = 1.0f / (float)NNODES;
    bool has2 = lane < (F2 - 32);
    float y0 = d_h2[(size_t)row * F2 + lane] - d_colsum[lane] * invN;
    float y1 = 0.f;
    if (has2) y1 = d_h2[(size_t)row * F2 + 32 + lane] - d_colsum[32 + lane] * invN;
    float ss = y0 * y0 + y1 * y1;
#pragma unroll
    for (int o = 16; o; o >>= 1) ss += __shfl_xor_sync(0xffffffffu, ss, o);
    float inv = rsqrtf(1e-6f + ss);
    float z0 = y0 * inv;
    float z1 = has2 ? y1 * inv : -1e30f;
    float mx = fmaxf(z0, z1);
#pragma unroll
    for (int o = 16; o; o >>= 1) mx = fmaxf(mx, __shfl_xor_sync(0xffffffffu, mx, o));
    float se = expf(z0 - mx) + (has2 ? expf(z1 - mx) : 0.f);
#pragma unroll
    for (int o = 16; o; o >>= 1) se += __shfl_xor_sync(0xffffffffu, se, o);
    float lse = logf(se);
    out[(size_t)row * F2 + lane] = z0 - mx - lse;
    if (has2) out[(size_t)row * F2 + 32 + lane] = z1 - mx - lse;
}

// ---------------- launch ----------------
extern "C" void kernel_launch(void* const* d_in, const int* in_sizes, int n_in,
                              void* d_out, int out_size) {
    const float* x   = (const float*)d_in[0];
    const void*  eix = d_in[1];
    const float* W1  = (const float*)d_in[2];
    const float* b1  = (const float*)d_in[3];
    const float* W2  = (const float*)d_in[4];
    const float* b2  = (const float*)d_in[5];
    float* out = (float*)d_out;

    float *g1, *h1, *g2;
    cudaGetSymbolAddress((void**)&g1, d_g1);
    cudaGetSymbolAddress((void**)&h1, d_h1);
    cudaGetSymbolAddress((void**)&g2, d_g2);

    const int T = 256;
    k_init<<<(NNODES + T - 1) / T, T>>>();
    k_detect<<<1, 256>>>((const long long*)eix);
    k_cvt_count<<<(NEDGES + T - 1) / T, T>>>(eix);
    k_scan1<<<NB, SCAN_B>>>();
    k_scan2<<<1, 256>>>();
    k_scan3<<<(NNODES + T - 1) / T, T>>>();
    k_fill<<<(NEDGES + T - 1) / T, T>>>();

    // Layer 1
    k_gemm_rowscale<<<(NNODES + 127) / 128, 256>>>(x, W1, g1, NNODES, F1, F0);
    k_agg1<<<(NNODES * 16 + T - 1) / T, T>>>(b1);

    // Layer 2
    k_gemm_rowscale<<<(NNODES + 127) / 128, 256>>>(h1, W2, g2, NNODES, F2, F1);
    k_agg2<<<(NNODES * 16 + T - 1) / T, T>>>(b2);

    // PairNorm + log_softmax
    k_final<<<((long long)NNODES * 32 + T - 1) / T, T>>>(out);
}

// round 6
// speedup vs baseline: 1.9874x; 1.2259x over previous
#include <cuda_runtime.h>
#include <math.h>

#define NNODES 100000
#define NEDGES 1000000
#define F0 256
#define F1 64
#define F2 40
#define SCAN_B 512
#define NB ((NNODES + SCAN_B - 1) / SCAN_B)   // 196

// ---------------- scratch (static device globals; no allocation) ----------------
__device__ float d_g1[NNODES * F1];
__device__ float d_h1[NNODES * F1];
__device__ float d_g2[NNODES * F2];
__device__ float d_h2[NNODES * F2];
__device__ float d_colsum[64];
__device__ float d_dinv[NNODES];
__device__ int   d_src32[NEDGES];
__device__ int   d_dst32[NEDGES];
__device__ int   d_csrc[NEDGES];
__device__ int   d_cnt[NNODES];        // zero-initialized; re-zeroed by k_scan3 each run
__device__ int   d_rowptr[NNODES + 1];
__device__ int   d_cursor[NNODES];
__device__ int   d_blocksum[NB];

// ---------------- convert + per-dst histogram (int64/int32 detect per block) ----------------
__global__ void k_cvt_count(const void* __restrict__ e) {
    __shared__ int s_is64;
    int t = threadIdx.x;
    if (t < 32) {
        const long long* e64 = (const long long*)e;
        long long v0 = e64[t];
        long long v1 = e64[t + 32];
        bool ok = (v0 >= 0 && v0 < NNODES) && (v1 >= 0 && v1 < NNODES);
        unsigned m = __ballot_sync(0xffffffffu, ok);
        if (t == 0) s_is64 = (m == 0xffffffffu) ? 1 : 0;
    }
    __syncthreads();
    int idx = blockIdx.x * blockDim.x + t;
    if (idx >= NEDGES) return;
    int s, d;
    if (s_is64) {
        s = (int)((const long long*)e)[idx];
        d = (int)((const long long*)e)[NEDGES + idx];
    } else {
        s = ((const int*)e)[idx];
        d = ((const int*)e)[NEDGES + idx];
    }
    d_src32[idx] = s;
    d_dst32[idx] = d;
    atomicAdd(&d_cnt[d], 1);
}

// ---------------- 3-kernel exclusive scan of d_cnt -> d_rowptr ----------------
__global__ void k_scan1() {
    __shared__ int sm[SCAN_B];
    int base = blockIdx.x * SCAN_B;
    int t = threadIdx.x;
    int v = (base + t < NNODES) ? d_cnt[base + t] : 0;
    sm[t] = v;
    __syncthreads();
    for (int o = 1; o < SCAN_B; o <<= 1) {
        int a = (t >= o) ? sm[t - o] : 0;
        __syncthreads();
        sm[t] += a;
        __syncthreads();
    }
    if (base + t < NNODES) d_rowptr[base + t] = sm[t] - v;
    if (t == SCAN_B - 1) d_blocksum[blockIdx.x] = sm[t];
}

__global__ void k_scan2() {
    __shared__ int sm[256];
    int t = threadIdx.x;
    if (t < 64) d_colsum[t] = 0.f;          // fold colsum init here (single block)
    int v = (t < NB) ? d_blocksum[t] : 0;
    sm[t] = v;
    __syncthreads();
    for (int o = 1; o < 256; o <<= 1) {
        int a = (t >= o) ? sm[t - o] : 0;
        __syncthreads();
        sm[t] += a;
        __syncthreads();
    }
    if (t < NB) d_blocksum[t] = sm[t] - v;
}

__global__ void k_scan3() {
    int i = blockIdx.x * blockDim.x + threadIdx.x;
    if (i >= NNODES) return;
    int rp = d_rowptr[i] + d_blocksum[i / SCAN_B];
    d_rowptr[i] = rp;
    d_cursor[i] = rp;
    d_dinv[i] = rsqrtf(1.0f + (float)d_cnt[i]);
    d_cnt[i] = 0;                           // reset for next graph replay
    if (i == 0) d_rowptr[NNODES] = NEDGES;
}

// ---------------- fill CSR ----------------
__global__ void k_fill() {
    int idx = blockIdx.x * blockDim.x + threadIdx.x;
    if (idx >= NEDGES) return;
    int dst = d_dst32[idx];
    int pos = atomicAdd(&d_cursor[dst], 1);
    d_csrc[pos] = d_src32[idx];
}

// ---------------- TF32 tensor-core GEMM: C = dinv[r] * (A@B) ----------------
// BM=128 BN=64 BK=16, 256 threads = 8 warps (4 M x 2 N), warp tile 32x32.
// mma.sync.m16n8k8 tf32. Smem padded so fragment LDS.32 is bank-conflict-free.
__device__ __forceinline__ unsigned f2tf32(float f) {
    unsigned u;
    asm("cvt.rna.tf32.f32 %0, %1;" : "=r"(u) : "f"(f));
    return u;
}

__global__ __launch_bounds__(256) void k_gemm_tf32(
    const float* __restrict__ A, const float* __restrict__ B,
    float* __restrict__ C, int M, int N, int K) {
    const int BM = 128, BK = 16;
    __shared__ unsigned As[BK][BM + 8];   // 136 % 32 = 8 -> disjoint bank octets per k
    __shared__ unsigned Bs[BK][64 + 8];   // 72 % 32 = 8
    int tid = threadIdx.x;
    int rowBase = blockIdx.x * BM;
    int warpId = tid >> 5;
    int lane = tid & 31;
    int g = lane >> 2;                    // 0..7
    int t4 = lane & 3;                    // 0..3
    int warpM = warpId & 3;               // 0..3
    int warpN = warpId >> 2;              // 0..1
    int m0 = warpM * 32;
    int n0 = warpN * 32;

    float acc[2][4][4];
#pragma unroll
    for (int mt = 0; mt < 2; mt++)
#pragma unroll
        for (int nt = 0; nt < 4; nt++)
#pragma unroll
            for (int i = 0; i < 4; i++) acc[mt][nt][i] = 0.f;

    for (int k0 = 0; k0 < K; k0 += BK) {
        // A tile: 128x16 floats = 512 float4s, 2 per thread, transposed + cvt
#pragma unroll
        for (int v = 0; v < 2; v++) {
            int vec = tid + v * 256;
            int row = vec >> 2;
            int col = (vec & 3) * 4;
            float4 av = make_float4(0.f, 0.f, 0.f, 0.f);
            int gr = rowBase + row;
            if (gr < M) av = *(const float4*)(A + (size_t)gr * K + k0 + col);
            As[col + 0][row] = f2tf32(av.x);
            As[col + 1][row] = f2tf32(av.y);
            As[col + 2][row] = f2tf32(av.z);
            As[col + 3][row] = f2tf32(av.w);
        }
        // B tile: 16x64, 1 float4 per thread + cvt
        {
            int br = tid >> 4;
            int bc = (tid & 15) * 4;
            float4 bv = make_float4(0.f, 0.f, 0.f, 0.f);
            if (bc < N) bv = *(const float4*)(B + (size_t)(k0 + br) * N + bc);
            Bs[br][bc + 0] = f2tf32(bv.x);
            Bs[br][bc + 1] = f2tf32(bv.y);
            Bs[br][bc + 2] = f2tf32(bv.z);
            Bs[br][bc + 3] = f2tf32(bv.w);
        }
        __syncthreads();
#pragma unroll
        for (int ks = 0; ks < 2; ks++) {
            int kb = ks * 8;
            unsigned af[2][4], bf[4][2];
#pragma unroll
            for (int mt = 0; mt < 2; mt++) {
                int m = m0 + mt * 16 + g;
                af[mt][0] = As[kb + t4][m];
                af[mt][1] = As[kb + t4][m + 8];
                af[mt][2] = As[kb + t4 + 4][m];
                af[mt][3] = As[kb + t4 + 4][m + 8];
            }
#pragma unroll
            for (int nt = 0; nt < 4; nt++) {
                int n = n0 + nt * 8 + g;
                bf[nt][0] = Bs[kb + t4][n];
                bf[nt][1] = Bs[kb + t4 + 4][n];
            }
#pragma unroll
            for (int mt = 0; mt < 2; mt++)
#pragma unroll
                for (int nt = 0; nt < 4; nt++) {
                    asm volatile(
                        "mma.sync.aligned.m16n8k8.row.col.f32.tf32.tf32.f32 "
                        "{%0,%1,%2,%3}, {%4,%5,%6,%7}, {%8,%9}, {%0,%1,%2,%3};"
                        : "+f"(acc[mt][nt][0]), "+f"(acc[mt][nt][1]),
                          "+f"(acc[mt][nt][2]), "+f"(acc[mt][nt][3])
                        : "r"(af[mt][0]), "r"(af[mt][1]), "r"(af[mt][2]), "r"(af[mt][3]),
                          "r"(bf[nt][0]), "r"(bf[nt][1]));
                }
        }
        __syncthreads();
    }
    // Epilogue: c0,c1 -> (row g, cols 2t4,2t4+1); c2,c3 -> (row g+8)
#pragma unroll
    for (int mt = 0; mt < 2; mt++) {
#pragma unroll
        for (int half = 0; half < 2; half++) {
            int r = rowBase + m0 + mt * 16 + half * 8 + g;
            if (r >= M) continue;
            float s = d_dinv[r];
#pragma unroll
            for (int nt = 0; nt < 4; nt++) {
                int c = n0 + nt * 8 + 2 * t4;
                if (c < N) {
                    float2 o;
                    o.x = acc[mt][nt][half * 2 + 0] * s;
                    o.y = acc[mt][nt][half * 2 + 1] * s;
                    *(float2*)(C + (size_t)r * N + c) = o;
                }
            }
        }
    }
}

// ---------------- layer-1 aggregation: gather + self loop + bias + relu ----------------
__global__ __launch_bounds__(256) void k_agg1(const float* __restrict__ b1) {
    int g = (blockIdx.x * blockDim.x + threadIdx.x) >> 4;
    int lane = threadIdx.x & 15;
    if (g >= NNODES) return;
    int start = d_rowptr[g];
    int end = d_rowptr[g + 1];
    const float4* G = (const float4*)d_g1;
    float4 acc = __ldg(&G[(size_t)g * 16 + lane]);   // self loop
    int e = start;
    for (; e + 1 < end; e += 2) {
        int s0 = __ldg(&d_csrc[e]);
        int s1 = __ldg(&d_csrc[e + 1]);
        float4 v0 = __ldg(&G[(size_t)s0 * 16 + lane]);
        float4 v1 = __ldg(&G[(size_t)s1 * 16 + lane]);
        acc.x += v0.x + v1.x;
        acc.y += v0.y + v1.y;
        acc.z += v0.z + v1.z;
        acc.w += v0.w + v1.w;
    }
    if (e < end) {
        int s0 = __ldg(&d_csrc[e]);
        float4 v = __ldg(&G[(size_t)s0 * 16 + lane]);
        acc.x += v.x; acc.y += v.y; acc.z += v.z; acc.w += v.w;
    }
    float s = d_dinv[g];
    int c = lane * 4;
    float4 o;
    o.x = fmaxf(s * acc.x + __ldg(b1 + c + 0), 0.f);
    o.y = fmaxf(s * acc.y + __ldg(b1 + c + 1), 0.f);
    o.z = fmaxf(s * acc.z + __ldg(b1 + c + 2), 0.f);
    o.w = fmaxf(s * acc.w + __ldg(b1 + c + 3), 0.f);
    ((float4*)d_h1)[(size_t)g * 16 + lane] = o;
}

// ---------------- layer-2 aggregation + bias + column sums ----------------
__global__ __launch_bounds__(256) void k_agg2(const float* __restrict__ b2) {
    __shared__ float scol[F2];
    int t = threadIdx.x;
    if (t < F2) scol[t] = 0.f;
    __syncthreads();
    int g = (blockIdx.x * blockDim.x + t) >> 4;
    int lane = t & 15;
    bool active = (g < NNODES) && (lane < 10);
    if (active) {
        int start = d_rowptr[g];
        int end = d_rowptr[g + 1];
        const float4* G = (const float4*)d_g2;
        float4 acc = __ldg(&G[(size_t)g * 10 + lane]);
        int e = start;
        for (; e + 1 < end; e += 2) {
            int s0 = __ldg(&d_csrc[e]);
            int s1 = __ldg(&d_csrc[e + 1]);
            float4 v0 = __ldg(&G[(size_t)s0 * 10 + lane]);
            float4 v1 = __ldg(&G[(size_t)s1 * 10 + lane]);
            acc.x += v0.x + v1.x;
            acc.y += v0.y + v1.y;
            acc.z += v0.z + v1.z;
            acc.w += v0.w + v1.w;
        }
        if (e < end) {
            int s0 = __ldg(&d_csrc[e]);
            float4 v = __ldg(&G[(size_t)s0 * 10 + lane]);
            acc.x += v.x; acc.y += v.y; acc.z += v.z; acc.w += v.w;
        }
        float s = d_dinv[g];
        int c = lane * 4;
        float4 o;
        o.x = s * acc.x + __ldg(b2 + c + 0);
        o.y = s * acc.y + __ldg(b2 + c + 1);
        o.z = s * acc.z + __ldg(b2 + c + 2);
        o.w = s * acc.w + __ldg(b2 + c + 3);
        ((float4*)d_h2)[(size_t)g * 10 + lane] = o;
        atomicAdd(&scol[c + 0], o.x);
        atomicAdd(&scol[c + 1], o.y);
        atomicAdd(&scol[c + 2], o.z);
        atomicAdd(&scol[c + 3], o.w);
    }
    __syncthreads();
    if (t < F2) atomicAdd(&d_colsum[t], scol[t]);
}

// ---------------- PairNorm-SI + log_softmax, one warp per row ----------------
__global__ void k_final(float* __restrict__ out) {
    int gt = blockIdx.x * blockDim.x + threadIdx.x;
    int row = gt >> 5;
    int lane = gt & 31;
    if (row >= NNODES) return;
    const float invN = 1.0f / (float)NNODES;
    bool has2 = lane < (F2 - 32);
    float y0 = d_h2[(size_t)row * F2 + lane] - d_colsum[lane] * invN;
    float y1 = 0.f;
    if (has2) y1 = d_h2[(size_t)row * F2 + 32 + lane] - d_colsum[32 + lane] * invN;
    float ss = y0 * y0 + y1 * y1;
#pragma unroll
    for (int o = 16; o; o >>= 1) ss += __shfl_xor_sync(0xffffffffu, ss, o);
    float inv = rsqrtf(1e-6f + ss);
    float z0 = y0 * inv;
    float z1 = has2 ? y1 * inv : -1e30f;
    float mx = fmaxf(z0, z1);
#pragma unroll
    for (int o = 16; o; o >>= 1) mx = fmaxf(mx, __shfl_xor_sync(0xffffffffu, mx, o));
    float se = expf(z0 - mx) + (has2 ? expf(z1 - mx) : 0.f);
#pragma unroll
    for (int o = 16; o; o >>= 1) se += __shfl_xor_sync(0xffffffffu, se, o);
    float lse = logf(se);
    out[(size_t)row * F2 + lane] = z0 - mx - lse;
    if (has2) out[(size_t)row * F2 + 32 + lane] = z1 - mx - lse;
}

// ---------------- launch ----------------
extern "C" void kernel_launch(void* const* d_in, const int* in_sizes, int n_in,
                              void* d_out, int out_size) {
    const float* x   = (const float*)d_in[0];
    const void*  eix = d_in[1];
    const float* W1  = (const float*)d_in[2];
    const float* b1  = (const float*)d_in[3];
    const float* W2  = (const float*)d_in[4];
    const float* b2  = (const float*)d_in[5];
    float* out = (float*)d_out;

    float *g1, *h1, *g2;
    cudaGetSymbolAddress((void**)&g1, d_g1);
    cudaGetSymbolAddress((void**)&h1, d_h1);
    cudaGetSymbolAddress((void**)&g2, d_g2);

    const int T = 256;
    // exactly 5 launches before GEMM1 so ncu (-s 5 -c 1) captures the GEMM
    k_cvt_count<<<(NEDGES + T - 1) / T, T>>>(eix);
    k_scan1<<<NB, SCAN_B>>>();
    k_scan2<<<1, 256>>>();
    k_scan3<<<(NNODES + T - 1) / T, T>>>();
    k_fill<<<(NEDGES + T - 1) / T, T>>>();

    // Layer 1
    k_gemm_tf32<<<(NNODES + 127) / 128, 256>>>(x, W1, g1, NNODES, F1, F0);
    k_agg1<<<(NNODES * 16 + T - 1) / T, T>>>(b1);

    // Layer 2
    k_gemm_tf32<<<(NNODES + 127) / 128, 256>>>(h1, W2, g2, NNODES, F2, F1);
    k_agg2<<<(NNODES * 16 + T - 1) / T, T>>>(b2);

    // PairNorm + log_softmax
    k_final<<<((long long)NNODES * 32 + T - 1) / T, T>>>(out);
}

// round 7
// speedup vs baseline: 2.1843x; 1.0991x over previous
#include <cuda_runtime.h>
#include <math.h>

#define NNODES 100000
#define NEDGES 1000000
#define F0 256
#define F1 64
#define F2 40
#define SCAN_B 512
#define NB ((NNODES + SCAN_B - 1) / SCAN_B)   // 196

// ---------------- scratch (static device globals; no allocation) ----------------
__device__ float d_g1[NNODES * F1];    // u1 = x @ W1 (unscaled)
__device__ float d_h1[NNODES * F1];
__device__ float d_g2[NNODES * F2];    // u2 = h1 @ W2 (unscaled)
__device__ float d_h2[NNODES * F2];
__device__ float d_colsum[64];
__device__ float d_dinv[NNODES];
__device__ int   d_csrc[NEDGES];
__device__ int   d_cnt[NNODES];        // zero at t=0; re-zeroed by k_scan3 each run
__device__ int   d_rowptr[NNODES + 1];
__device__ int   d_cursor[NNODES];
__device__ int   d_blocksum[NB];

// ---------------- per-block int64/int32 detection helper ----------------
__device__ __forceinline__ int detect_is64(const void* e, int t) {
    __shared__ int s_is64;
    if (t < 32) {
        const long long* e64 = (const long long*)e;
        long long v0 = e64[t];
        long long v1 = e64[t + 32];
        bool ok = (v0 >= 0 && v0 < NNODES) && (v1 >= 0 && v1 < NNODES);
        unsigned m = __ballot_sync(0xffffffffu, ok);
        if (t == 0) s_is64 = (m == 0xffffffffu) ? 1 : 0;
    }
    __syncthreads();
    return s_is64;
}

// ---------------- per-dst histogram (reads raw edge list) ----------------
__global__ void k_count(const void* __restrict__ e) {
    int t = threadIdx.x;
    int is64 = detect_is64(e, t);
    int idx = blockIdx.x * blockDim.x + t;
    if (idx >= NEDGES) return;
    int d = is64 ? (int)((const long long*)e)[NEDGES + idx]
                 : ((const int*)e)[NEDGES + idx];
    atomicAdd(&d_cnt[d], 1);
}

// ---------------- 3-kernel exclusive scan of d_cnt -> d_rowptr ----------------
__global__ void k_scan1() {
    __shared__ int sm[SCAN_B];
    int base = blockIdx.x * SCAN_B;
    int t = threadIdx.x;
    int v = (base + t < NNODES) ? d_cnt[base + t] : 0;
    sm[t] = v;
    __syncthreads();
    for (int o = 1; o < SCAN_B; o <<= 1) {
        int a = (t >= o) ? sm[t - o] : 0;
        __syncthreads();
        sm[t] += a;
        __syncthreads();
    }
    if (base + t < NNODES) d_rowptr[base + t] = sm[t] - v;
    if (t == SCAN_B - 1) d_blocksum[blockIdx.x] = sm[t];
}

__global__ void k_scan2() {
    __shared__ int sm[256];
    int t = threadIdx.x;
    if (t < 64) d_colsum[t] = 0.f;          // fold colsum init here (single block)
    int v = (t < NB) ? d_blocksum[t] : 0;
    sm[t] = v;
    __syncthreads();
    for (int o = 1; o < 256; o <<= 1) {
        int a = (t >= o) ? sm[t - o] : 0;
        __syncthreads();
        sm[t] += a;
        __syncthreads();
    }
    if (t < NB) d_blocksum[t] = sm[t] - v;
}

__global__ void k_scan3() {
    int i = blockIdx.x * blockDim.x + threadIdx.x;
    if (i >= NNODES) return;
    int rp = d_rowptr[i] + d_blocksum[i / SCAN_B];
    d_rowptr[i] = rp;
    d_cursor[i] = rp;
    d_dinv[i] = rsqrtf(1.0f + (float)d_cnt[i]);
    d_cnt[i] = 0;                           // reset for next graph replay
    if (i == 0) d_rowptr[NNODES] = NEDGES;
}

// ---------------- fill CSR (reads raw edge list) ----------------
__global__ void k_fill(const void* __restrict__ e) {
    int t = threadIdx.x;
    int is64 = detect_is64(e, t);
    int idx = blockIdx.x * blockDim.x + t;
    if (idx >= NEDGES) return;
    int s, d;
    if (is64) {
        s = (int)((const long long*)e)[idx];
        d = (int)((const long long*)e)[NEDGES + idx];
    } else {
        s = ((const int*)e)[idx];
        d = ((const int*)e)[NEDGES + idx];
    }
    int pos = atomicAdd(&d_cursor[d], 1);
    d_csrc[pos] = s;
}

// ---------------- TF32 tensor-core GEMM: C = A@B (unscaled) ----------------
__device__ __forceinline__ unsigned f2tf32(float f) {
    unsigned u;
    asm("cvt.rna.tf32.f32 %0, %1;" : "=r"(u) : "f"(f));
    return u;
}

__global__ __launch_bounds__(256) void k_gemm_tf32(
    const float* __restrict__ A, const float* __restrict__ B,
    float* __restrict__ C, int M, int N, int K) {
    const int BM = 128, BK = 16;
    __shared__ unsigned As[BK][BM + 8];
    __shared__ unsigned Bs[BK][64 + 8];
    int tid = threadIdx.x;
    int rowBase = blockIdx.x * BM;
    int warpId = tid >> 5;
    int lane = tid & 31;
    int g = lane >> 2;
    int t4 = lane & 3;
    int warpM = warpId & 3;
    int warpN = warpId >> 2;
    int m0 = warpM * 32;
    int n0 = warpN * 32;

    float acc[2][4][4];
#pragma unroll
    for (int mt = 0; mt < 2; mt++)
#pragma unroll
        for (int nt = 0; nt < 4; nt++)
#pragma unroll
            for (int i = 0; i < 4; i++) acc[mt][nt][i] = 0.f;

    for (int k0 = 0; k0 < K; k0 += BK) {
#pragma unroll
        for (int v = 0; v < 2; v++) {
            int vec = tid + v * 256;
            int row = vec >> 2;
            int col = (vec & 3) * 4;
            float4 av = make_float4(0.f, 0.f, 0.f, 0.f);
            int gr = rowBase + row;
            if (gr < M) av = *(const float4*)(A + (size_t)gr * K + k0 + col);
            As[col + 0][row] = f2tf32(av.x);
            As[col + 1][row] = f2tf32(av.y);
            As[col + 2][row] = f2tf32(av.z);
            As[col + 3][row] = f2tf32(av.w);
        }
        {
            int br = tid >> 4;
            int bc = (tid & 15) * 4;
            float4 bv = make_float4(0.f, 0.f, 0.f, 0.f);
            if (bc < N) bv = *(const float4*)(B + (size_t)(k0 + br) * N + bc);
            Bs[br][bc + 0] = f2tf32(bv.x);
            Bs[br][bc + 1] = f2tf32(bv.y);
            Bs[br][bc + 2] = f2tf32(bv.z);
            Bs[br][bc + 3] = f2tf32(bv.w);
        }
        __syncthreads();
#pragma unroll
        for (int ks = 0; ks < 2; ks++) {
            int kb = ks * 8;
            unsigned af[2][4], bf[4][2];
#pragma unroll
            for (int mt = 0; mt < 2; mt++) {
                int m = m0 + mt * 16 + g;
                af[mt][0] = As[kb + t4][m];
                af[mt][1] = As[kb + t4][m + 8];
                af[mt][2] = As[kb + t4 + 4][m];
                af[mt][3] = As[kb + t4 + 4][m + 8];
            }
#pragma unroll
            for (int nt = 0; nt < 4; nt++) {
                int n = n0 + nt * 8 + g;
                bf[nt][0] = Bs[kb + t4][n];
                bf[nt][1] = Bs[kb + t4 + 4][n];
            }
#pragma unroll
            for (int mt = 0; mt < 2; mt++)
#pragma unroll
                for (int nt = 0; nt < 4; nt++) {
                    asm volatile(
                        "mma.sync.aligned.m16n8k8.row.col.f32.tf32.tf32.f32 "
                        "{%0,%1,%2,%3}, {%4,%5,%6,%7}, {%8,%9}, {%0,%1,%2,%3};"
                        : "+f"(acc[mt][nt][0]), "+f"(acc[mt][nt][1]),
                          "+f"(acc[mt][nt][2]), "+f"(acc[mt][nt][3])
                        : "r"(af[mt][0]), "r"(af[mt][1]), "r"(af[mt][2]), "r"(af[mt][3]),
                          "r"(bf[nt][0]), "r"(bf[nt][1]));
                }
        }
        __syncthreads();
    }
#pragma unroll
    for (int mt = 0; mt < 2; mt++) {
#pragma unroll
        for (int half = 0; half < 2; half++) {
            int r = rowBase + m0 + mt * 16 + half * 8 + g;
            if (r >= M) continue;
#pragma unroll
            for (int nt = 0; nt < 4; nt++) {
                int c = n0 + nt * 8 + 2 * t4;
                if (c < N) {
                    float2 o;
                    o.x = acc[mt][nt][half * 2 + 0];
                    o.y = acc[mt][nt][half * 2 + 1];
                    *(float2*)(C + (size_t)r * N + c) = o;
                }
            }
        }
    }
}

// ---------------- layer-1 aggregation: dinv-weighted gather + self + bias + relu ----------------
// out[d] = dinv[d]*( sum_{s->d} dinv[s]*u[s] + dinv[d]*u[d] ) + b1, relu
__global__ __launch_bounds__(256) void k_agg1(const float* __restrict__ b1) {
    int g = (blockIdx.x * blockDim.x + threadIdx.x) >> 4;
    int lane = threadIdx.x & 15;
    if (g >= NNODES) return;
    int start = d_rowptr[g];
    int end = d_rowptr[g + 1];
    const float4* G = (const float4*)d_g1;
    float sd = d_dinv[g];
    float4 u = __ldg(&G[(size_t)g * 16 + lane]);
    float4 acc = make_float4(sd * u.x, sd * u.y, sd * u.z, sd * u.w);  // self loop
    int e = start;
    for (; e + 3 < end; e += 4) {
        int s0 = __ldg(&d_csrc[e]);
        int s1 = __ldg(&d_csrc[e + 1]);
        int s2 = __ldg(&d_csrc[e + 2]);
        int s3 = __ldg(&d_csrc[e + 3]);
        float w0 = __ldg(&d_dinv[s0]);
        float w1 = __ldg(&d_dinv[s1]);
        float w2 = __ldg(&d_dinv[s2]);
        float w3 = __ldg(&d_dinv[s3]);
        float4 v0 = __ldg(&G[(size_t)s0 * 16 + lane]);
        float4 v1 = __ldg(&G[(size_t)s1 * 16 + lane]);
        float4 v2 = __ldg(&G[(size_t)s2 * 16 + lane]);
        float4 v3 = __ldg(&G[(size_t)s3 * 16 + lane]);
        acc.x += w0 * v0.x + w1 * v1.x + w2 * v2.x + w3 * v3.x;
        acc.y += w0 * v0.y + w1 * v1.y + w2 * v2.y + w3 * v3.y;
        acc.z += w0 * v0.z + w1 * v1.z + w2 * v2.z + w3 * v3.z;
        acc.w += w0 * v0.w + w1 * v1.w + w2 * v2.w + w3 * v3.w;
    }
    for (; e < end; e++) {
        int s0 = __ldg(&d_csrc[e]);
        float w0 = __ldg(&d_dinv[s0]);
        float4 v = __ldg(&G[(size_t)s0 * 16 + lane]);
        acc.x += w0 * v.x; acc.y += w0 * v.y; acc.z += w0 * v.z; acc.w += w0 * v.w;
    }
    int c = lane * 4;
    float4 o;
    o.x = fmaxf(sd * acc.x + __ldg(b1 + c + 0), 0.f);
    o.y = fmaxf(sd * acc.y + __ldg(b1 + c + 1), 0.f);
    o.z = fmaxf(sd * acc.z + __ldg(b1 + c + 2), 0.f);
    o.w = fmaxf(sd * acc.w + __ldg(b1 + c + 3), 0.f);
    ((float4*)d_h1)[(size_t)g * 16 + lane] = o;
}

// ---------------- layer-2 aggregation + bias + column sums ----------------
__global__ __launch_bounds__(256) void k_agg2(const float* __restrict__ b2) {
    __shared__ float scol[F2];
    int t = threadIdx.x;
    if (t < F2) scol[t] = 0.f;
    __syncthreads();
    int g = (blockIdx.x * blockDim.x + t) >> 4;
    int lane = t & 15;
    bool active = (g < NNODES) && (lane < 10);
    if (active) {
        int start = d_rowptr[g];
        int end = d_rowptr[g + 1];
        const float4* G = (const float4*)d_g2;
        float sd = d_dinv[g];
        float4 u = __ldg(&G[(size_t)g * 10 + lane]);
        float4 acc = make_float4(sd * u.x, sd * u.y, sd * u.z, sd * u.w);
        int e = start;
        for (; e + 1 < end; e += 2) {
            int s0 = __ldg(&d_csrc[e]);
            int s1 = __ldg(&d_csrc[e + 1]);
            float w0 = __ldg(&d_dinv[s0]);
            float w1 = __ldg(&d_dinv[s1]);
            float4 v0 = __ldg(&G[(size_t)s0 * 10 + lane]);
            float4 v1 = __ldg(&G[(size_t)s1 * 10 + lane]);
            acc.x += w0 * v0.x + w1 * v1.x;
            acc.y += w0 * v0.y + w1 * v1.y;
            acc.z += w0 * v0.z + w1 * v1.z;
            acc.w += w0 * v0.w + w1 * v1.w;
        }
        if (e < end) {
            int s0 = __ldg(&d_csrc[e]);
            float w0 = __ldg(&d_dinv[s0]);
            float4 v = __ldg(&G[(size_t)s0 * 10 + lane]);
            acc.x += w0 * v.x; acc.y += w0 * v.y; acc.z += w0 * v.z; acc.w += w0 * v.w;
        }
        int c = lane * 4;
        float4 o;
        o.x = sd * acc.x + __ldg(b2 + c + 0);
        o.y = sd * acc.y + __ldg(b2 + c + 1);
        o.z = sd * acc.z + __ldg(b2 + c + 2);
        o.w = sd * acc.w + __ldg(b2 + c + 3);
        ((float4*)d_h2)[(size_t)g * 10 + lane] = o;
        atomicAdd(&scol[c + 0], o.x);
        atomicAdd(&scol[c + 1], o.y);
        atomicAdd(&scol[c + 2], o.z);
        atomicAdd(&scol[c + 3], o.w);
    }
    __syncthreads();
    if (t < F2) atomicAdd(&d_colsum[t], scol[t]);
}

// ---------------- PairNorm-SI + log_softmax, one warp per row ----------------
__global__ void k_final(float* __restrict__ out) {
    int gt = blockIdx.x * blockDim.x + threadIdx.x;
    int row = gt >> 5;
    int lane = gt & 31;
    if (row >= NNODES) return;
    const float invN = 1.0f / (float)NNODES;
    bool has2 = lane < (F2 - 32);
    float y0 = d_h2[(size_t)row * F2 + lane] - d_colsum[lane] * invN;
    float y1 = 0.f;
    if (has2) y1 = d_h2[(size_t)row * F2 + 32 + lane] - d_colsum[32 + lane] * invN;
    float ss = y0 * y0 + y1 * y1;
#pragma unroll
    for (int o = 16; o; o >>= 1) ss += __shfl_xor_sync(0xffffffffu, ss, o);
    float inv = rsqrtf(1e-6f + ss);
    float z0 = y0 * inv;
    float z1 = has2 ? y1 * inv : -1e30f;
    float mx = fmaxf(z0, z1);
#pragma unroll
    for (int o = 16; o; o >>= 1) mx = fmaxf(mx, __shfl_xor_sync(0xffffffffu, mx, o));
    float se = expf(z0 - mx) + (has2 ? expf(z1 - mx) : 0.f);
#pragma unroll
    for (int o = 16; o; o >>= 1) se += __shfl_xor_sync(0xffffffffu, se, o);
    float lse = logf(se);
    out[(size_t)row * F2 + lane] = z0 - mx - lse;
    if (has2) out[(size_t)row * F2 + 32 + lane] = z1 - mx - lse;
}

// ---------------- launch ----------------
extern "C" void kernel_launch(void* const* d_in, const int* in_sizes, int n_in,
                              void* d_out, int out_size) {
    const float* x   = (const float*)d_in[0];
    const void*  eix = d_in[1];
    const float* W1  = (const float*)d_in[2];
    const float* b1  = (const float*)d_in[3];
    const float* W2  = (const float*)d_in[4];
    const float* b2  = (const float*)d_in[5];
    float* out = (float*)d_out;

    // one-time resources (created on first call = the non-captured correctness run)
    static cudaStream_t s_aux = []() {
        cudaStream_t s; cudaStreamCreateWithFlags(&s, cudaStreamNonBlocking); return s;
    }();
    static cudaEvent_t e_fork = []() {
        cudaEvent_t e; cudaEventCreateWithFlags(&e, cudaEventDisableTiming); return e;
    }();
    static cudaEvent_t e_join = []() {
        cudaEvent_t e; cudaEventCreateWithFlags(&e, cudaEventDisableTiming); return e;
    }();

    float *g1, *h1, *g2;
    cudaGetSymbolAddress((void**)&g1, d_g1);
    cudaGetSymbolAddress((void**)&h1, d_h1);
    cudaGetSymbolAddress((void**)&g2, d_g2);

    const int T = 256;

    // Fork: GEMM1 (independent of CSR build) on aux stream
    cudaEventRecord(e_fork, 0);
    cudaStreamWaitEvent(s_aux, e_fork, 0);
    k_gemm_tf32<<<(NNODES + 127) / 128, 256, 0, s_aux>>>(x, W1, g1, NNODES, F1, F0);
    cudaEventRecord(e_join, s_aux);

    // CSR build on the main (capture) stream
    k_count<<<(NEDGES + T - 1) / T, T>>>(eix);
    k_scan1<<<NB, SCAN_B>>>();
    k_scan2<<<1, 256>>>();
    k_scan3<<<(NNODES + T - 1) / T, T>>>();
    k_fill<<<(NEDGES + T - 1) / T, T>>>(eix);

    // Join, then the dependent chain
    cudaStreamWaitEvent(0, e_join, 0);
    k_agg1<<<(NNODES * 16 + T - 1) / T, T>>>(b1);
    k_gemm_tf32<<<(NNODES + 127) / 128, 256>>>(h1, W2, g2, NNODES, F2, F1);
    k_agg2<<<(NNODES * 16 + T - 1) / T, T>>>(b2);
    k_final<<<((long long)NNODES * 32 + T - 1) / T, T>>>(out);
}